// round 3
// baseline (speedup 1.0000x reference)
#include <cuda_runtime.h>
#include <cuda_bf16.h>

// Dynamic per-pixel depthwise 3x3 conv, stride 1, pad 1.
// input : [B=8, C=64, H=128, W=128]           float32
// weight: [B, C, 3, 3, outH=128, outW=128]    float32
// out   : [B, C, 128, 128]                    float32
//
// Pure HBM-bound: ~341 MB DRAM traffic (weights 302 MB read-once dominate).
// One thread = 16 consecutive ow pixels. Per kh-row:
//   input : 4 aligned float4 __ldg + 2 predicated halo scalars (L1/L2 reuse)
//   weight: 3 taps x 4 float4 __ldcs (streaming, evict-first)
// Output: 4 x __stcs float4 (write-once, don't pollute L2).
// Rows processed one kh at a time so input regs are reused -> ~70 regs.

#define B_  8
#define C_  64
#define H_  128
#define W_  128
#define HW_ (H_ * W_)

__global__ __launch_bounds__(256)
void dydconv_kernel(const float* __restrict__ input,
                    const float* __restrict__ weight,
                    float* __restrict__ out)
{
    // one thread = 16 pixels along ow
    const int tid = blockIdx.x * blockDim.x + threadIdx.x;
    const int grp_per_row = W_ / 16;                  // 8
    const int ow = (tid & (grp_per_row - 1)) * 16;    // 0,16,...,112
    int t = tid >> 3;
    const int oh = t & (H_ - 1);
    const int bc = t >> 7;                            // 0..511

    // weight layout: (((bc*3 + kh)*3 + kw)*H_ + oh)*W_ + ow
    const long wbase = ((long)bc * 9) * (long)HW_ + (long)oh * W_ + ow;
    const int ibase = bc * HW_ + oh * W_ + ow;

    float4 acc[4];
    #pragma unroll
    for (int q = 0; q < 4; ++q) acc[q] = make_float4(0.f, 0.f, 0.f, 0.f);

    #pragma unroll
    for (int kh = 0; kh < 3; ++kh) {
        const int ih = oh + kh - 1;

        // input row [ow-1 .. ow+16] -> 18 floats
        float r[18];
        if (ih >= 0 && ih < H_) {
            const float* __restrict__ irow = input + bc * HW_ + ih * W_ + ow;
            #pragma unroll
            for (int q = 0; q < 4; ++q) {
                const float4 v = __ldg(reinterpret_cast<const float4*>(irow + 4 * q));
                r[1 + 4 * q + 0] = v.x; r[1 + 4 * q + 1] = v.y;
                r[1 + 4 * q + 2] = v.z; r[1 + 4 * q + 3] = v.w;
            }
            r[0]  = (ow > 0)        ? __ldg(irow - 1)  : 0.f;
            r[17] = (ow + 16 < W_)  ? __ldg(irow + 16) : 0.f;
        } else {
            #pragma unroll
            for (int tt = 0; tt < 18; ++tt) r[tt] = 0.f;
        }

        // 3 taps of this row; weights streamed (read-once)
        #pragma unroll
        for (int kw = 0; kw < 3; ++kw) {
            const float* wp = weight + wbase + (long)(kh * 3 + kw) * HW_;
            #pragma unroll
            for (int q = 0; q < 4; ++q) {
                const float4 w = __ldcs(reinterpret_cast<const float4*>(wp + 4 * q));
                acc[q].x = fmaf(w.x, r[kw + 4 * q + 0], acc[q].x);
                acc[q].y = fmaf(w.y, r[kw + 4 * q + 1], acc[q].y);
                acc[q].z = fmaf(w.z, r[kw + 4 * q + 2], acc[q].z);
                acc[q].w = fmaf(w.w, r[kw + 4 * q + 3], acc[q].w);
            }
        }
    }

    float* op = out + ibase;
    #pragma unroll
    for (int q = 0; q < 4; ++q)
        __stcs(reinterpret_cast<float4*>(op + 4 * q), acc[q]);
}

extern "C" void kernel_launch(void* const* d_in, const int* in_sizes, int n_in,
                              void* d_out, int out_size)
{
    const float* input  = (const float*)d_in[0];
    const float* weight = (const float*)d_in[1];
    float* out = (float*)d_out;

    const int total_thr = B_ * C_ * H_ * (W_ / 16);   // 524,288
    const int threads = 256;
    const int blocks = total_thr / threads;           // 2048
    dydconv_kernel<<<blocks, threads>>>(input, weight, out);
}

// round 4
// speedup vs baseline: 1.4332x; 1.4332x over previous
#include <cuda_runtime.h>
#include <cuda_bf16.h>

// Dynamic per-pixel depthwise 3x3 conv, stride 1, pad 1.
// input : [B=8, C=64, H=128, W=128]           float32
// weight: [B, C, 3, 3, outH=128, outW=128]    float32
// out   : [B, C, 128, 128]                    float32
//
// HBM-bound (~341 MB DRAM traffic; 302 MB is read-once weights).
// One thread = 4 px x 2 adjacent oh rows:
//   - warp = 32 lanes x 4px = one FULL 128-px row per request -> every weight
//     LDG.128 is perfectly coalesced (nL=4), two independent rows per tap
//     give 18 in-flight float4 weight loads per thread (high MLP).
//   - the two output rows share 2 of 4 input rows (input loads -33%).

#define B_  8
#define C_  64
#define H_  128
#define W_  128
#define HW_ (H_ * W_)

__global__ __launch_bounds__(256)
void dydconv_kernel(const float* __restrict__ input,
                    const float* __restrict__ weight,
                    float* __restrict__ out)
{
    const int tid = blockIdx.x * blockDim.x + threadIdx.x;
    const int ow4 = (tid & 31) * 4;          // 0..124, lane-contiguous
    int t = tid >> 5;
    const int oh2 = (t & 63) * 2;            // row pair: oh2, oh2+1
    const int bc = t >> 6;                   // 0..511

    // weight layout: (((bc*3 + kh)*3 + kw)*H_ + oh)*W_ + ow
    const long wbase = ((long)bc * 9) * (long)HW_ + (long)oh2 * W_ + ow4;
    const int ibase = bc * HW_ + oh2 * W_ + ow4;

    // input rows ih = oh2-1 .. oh2+2 ; each needs [ow4-1 .. ow4+4] = 6 floats
    float r[4][6];
    #pragma unroll
    for (int rr = 0; rr < 4; ++rr) {
        const int ih = oh2 - 1 + rr;
        if (ih >= 0 && ih < H_) {
            const float* __restrict__ irow = input + bc * HW_ + ih * W_ + ow4;
            const float4 v = __ldg(reinterpret_cast<const float4*>(irow));
            r[rr][0] = (ow4 > 0)       ? __ldg(irow - 1) : 0.f;
            r[rr][5] = (ow4 + 4 < W_)  ? __ldg(irow + 4) : 0.f;
            r[rr][1] = v.x; r[rr][2] = v.y; r[rr][3] = v.z; r[rr][4] = v.w;
        } else {
            #pragma unroll
            for (int tt = 0; tt < 6; ++tt) r[rr][tt] = 0.f;
        }
    }

    float4 acc0 = make_float4(0.f, 0.f, 0.f, 0.f);  // row oh2
    float4 acc1 = make_float4(0.f, 0.f, 0.f, 0.f);  // row oh2+1

    #pragma unroll
    for (int kh = 0; kh < 3; ++kh) {
        #pragma unroll
        for (int kw = 0; kw < 3; ++kw) {
            const float* wp = weight + wbase + (long)(kh * 3 + kw) * HW_;
            const float4 w0 = __ldcs(reinterpret_cast<const float4*>(wp));        // tap row oh2
            const float4 w1 = __ldcs(reinterpret_cast<const float4*>(wp + W_));   // tap row oh2+1
            const float* ra = r[kh];        // input row oh2-1+kh
            const float* rb = r[kh + 1];    // input row oh2+kh
            acc0.x = fmaf(w0.x, ra[kw + 0], acc0.x);
            acc0.y = fmaf(w0.y, ra[kw + 1], acc0.y);
            acc0.z = fmaf(w0.z, ra[kw + 2], acc0.z);
            acc0.w = fmaf(w0.w, ra[kw + 3], acc0.w);
            acc1.x = fmaf(w1.x, rb[kw + 0], acc1.x);
            acc1.y = fmaf(w1.y, rb[kw + 1], acc1.y);
            acc1.z = fmaf(w1.z, rb[kw + 2], acc1.z);
            acc1.w = fmaf(w1.w, rb[kw + 3], acc1.w);
        }
    }

    *reinterpret_cast<float4*>(out + ibase)      = acc0;
    *reinterpret_cast<float4*>(out + ibase + W_) = acc1;
}

extern "C" void kernel_launch(void* const* d_in, const int* in_sizes, int n_in,
                              void* d_out, int out_size)
{
    const float* input  = (const float*)d_in[0];
    const float* weight = (const float*)d_in[1];
    float* out = (float*)d_out;

    const int total_thr = B_ * C_ * (H_ / 2) * (W_ / 4);  // 1,048,576
    const int threads = 256;
    const int blocks = total_thr / threads;               // 4096
    dydconv_kernel<<<blocks, threads>>>(input, weight, out);
}